// round 1
// baseline (speedup 1.0000x reference)
#include <cuda_runtime.h>
#include <cstddef>

#define BSZ   256
#define NN    2048
#define KK    64
#define KP1   65
#define NT    512
#define RPT   4          // rows per thread = NN/NT
#define NWARP (NT/32)
#define MAXIT 200
#define EPS_F 0.1f
#define SMALL_F 1e-20f

__device__ unsigned g_maxEnc;
__device__ unsigned g_minEnc;
__device__ int      g_anyMask;
__device__ float    g_alpha;
__device__ float    g_filled;
__device__ float    g_normPart[BSZ];

__device__ __forceinline__ float neg_inf_f(){ return __int_as_float(0xff800000); }

// order-preserving float->uint encoding (monotone increasing)
__device__ __forceinline__ unsigned encF(float f){
  unsigned u = __float_as_uint(f);
  return (u & 0x80000000u) ? ~u : (u | 0x80000000u);
}
__device__ __forceinline__ float decF(unsigned e){
  unsigned u = (e & 0x80000000u) ? (e & 0x7fffffffu) : ~e;
  return __uint_as_float(u);
}

__global__ void k_init(){
  g_maxEnc = 0u;
  g_minEnc = 0xffffffffu;
  g_anyMask = 0;
}

__global__ void k_reduce(const float* __restrict__ s){
  int i = blockIdx.x * blockDim.x + threadIdx.x;
  int stride = gridDim.x * blockDim.x;
  unsigned mx = 0u, mn = 0xffffffffu;
  unsigned any = 0u;
  float ninf = neg_inf_f();
  for (; i < BSZ*NN; i += stride){
    float x = s[i];
    bool neg = (x == ninf);
    any |= (neg ? 1u : 0u);
    unsigned e = encF(x);
    mx = max(mx, e);                       // max over raw s (-inf can't win unless all -inf)
    mn = min(mn, neg ? 0xffffffffu : e);   // min over where(mask, +inf, s)
  }
  mx  = __reduce_max_sync(0xffffffffu, mx);
  mn  = __reduce_min_sync(0xffffffffu, mn);
  any = __reduce_or_sync (0xffffffffu, any);
  if ((threadIdx.x & 31) == 0){
    atomicMax(&g_maxEnc, mx);
    atomicMin(&g_minEnc, mn);
    if (any) atomicOr(&g_anyMask, 1);
  }
}

__global__ void k_params(){
  float maxS = decF(g_maxEnc);
  float minS = decF(g_minEnc);
  float filled = minS - (maxS - minS);
  float minF = g_anyMask ? fminf(filled, minS) : minS;
  float maxF = fmaxf(maxS, minF);
  // Cmax = max over s in [minF,maxF], anchor a in {0..64} of (s-a)^2 ; convex -> corners
  float c1 = minF*minF, c2 = maxF*maxF;
  float c3 = (minF-64.f)*(minF-64.f), c4 = (maxF-64.f)*(maxF-64.f);
  float cmax = fmaxf(fmaxf(c1,c2), fmaxf(c3,c4));
  g_alpha  = 1.f/(EPS_F*cmax);
  g_filled = filled;
}

__global__ void __launch_bounds__(NT, 1) k_main(
    const float* __restrict__ scores,
    const float* __restrict__ W,
    float* __restrict__ out)
{
  __shared__ float sh_s[NN];
  __shared__ float sh_sort[NN];
  __shared__ float sh_cE[KP1];
  __shared__ float sh_coef[KP1];          // coef[a] = cE[a] * v[64-a]
  __shared__ float sh_red[NWARP*KP1];
  __shared__ float sh_tk[KK];
  __shared__ float sh_invZn[KK];
  __shared__ float sh_scalar[1];

  const int b    = blockIdx.x;
  const int tid  = threadIdx.x;
  const int wid  = tid >> 5;
  const int lane = tid & 31;
  const float alpha  = g_alpha;
  const float filled = g_filled;
  const float MU = 1.f/(float)NN;
  const float ninf = neg_inf_f();

  const float* sc = scores + (size_t)b*NN;

  #pragma unroll
  for (int j=0;j<RPT;j++){
    int n = tid + j*NT;
    float x = sc[n];
    if (x == ninf) x = filled;
    sh_s[n] = x;
  }
  if (tid < KP1){
    float a  = (float)tid;
    float ce = __expf(-alpha*a*a);
    sh_cE[tid]   = ce;
    sh_coef[tid] = ce * (1.f/(float)KP1);  // v0 = 1/65
  }
  __syncthreads();

  float w[RPT], y[RPT];
  #pragma unroll
  for (int j=0;j<RPT;j++) w[j] = __expf(2.f*alpha*sh_s[tid + j*NT]);

  // ================= Sinkhorn: 200 iterations =================
  #pragma unroll 1
  for (int it=0; it<MAXIT; ++it){
    // u-update: acc = sum_a coef[a] * w^a  (Horner);  y = u*p = MU/acc
    float acc[RPT];
    #pragma unroll
    for (int j=0;j<RPT;j++) acc[j] = sh_coef[KK];
    #pragma unroll
    for (int a=KK-1;a>=0;--a){
      float f = sh_coef[a];
      #pragma unroll
      for (int j=0;j<RPT;j++) acc[j] = fmaf(acc[j], w[j], f);
    }
    #pragma unroll
    for (int j=0;j<RPT;j++) y[j] = __fdividef(MU, acc[j]);

    // v-update power sums: m_a = sum_n y_n w_n^a, reduced across the CTA
    float t0=y[0], t1=y[1], t2=y[2], t3=y[3];
    #pragma unroll
    for (int a=0;a<KP1;a++){
      float mv = (t0+t1)+(t2+t3);
      #pragma unroll
      for (int o=16;o>0;o>>=1) mv += __shfl_xor_sync(0xffffffffu, mv, o);
      if (lane==0) sh_red[wid*KP1+a] = mv;
      if (a < KK){ t0*=w[0]; t1*=w[1]; t2*=w[2]; t3*=w[3]; }
    }
    __syncthreads();
    if (tid < KP1){                       // tid == a ; k = 64-a
      float mm = 0.f;
      #pragma unroll
      for (int q=0;q<NWARP;q++) mm += sh_red[q*KP1+tid];
      float nuv = (tid==0) ? ((float)(NN-KK)/(float)NN) : MU;
      float vk  = nuv / (sh_cE[tid]*mm);
      sh_coef[tid] = sh_cE[tid]*vk;       // fold v straight into next coef
    }
    __syncthreads();
  }
  // y == u*p (final), sh_coef == cE[a]*v_final[64-a]

  // ================= sort s (bitonic, ascending) =================
  #pragma unroll
  for (int j=0;j<RPT;j++) sh_sort[tid+j*NT] = sh_s[tid+j*NT];
  __syncthreads();
  for (int kk2=2; kk2<=NN; kk2<<=1){
    for (int jj=kk2>>1; jj>0; jj>>=1){
      #pragma unroll
      for (int j=0;j<RPT;j++){
        int i = tid + j*NT;
        int ixj = i ^ jj;
        if (ixj > i){
          float va = sh_sort[i], vb = sh_sort[ixj];
          bool asc = ((i & kk2) == 0);
          if ((va > vb) == asc){ sh_sort[i]=vb; sh_sort[ixj]=va; }
        }
      }
      __syncthreads();
    }
  }

  // ================= tau and top-k =================
  {
    float part = 0.f;
    #pragma unroll
    for (int j=0;j<RPT;j++){ int n=tid+j*NT; part += sh_sort[n]*W[n]; }
    #pragma unroll
    for (int o=16;o>0;o>>=1) part += __shfl_xor_sync(0xffffffffu, part, o);
    if (lane==0) sh_red[wid] = part;
    __syncthreads();
    if (tid==0){
      float tau=0.f;
      for (int q=0;q<NWARP;q++) tau += sh_red[q];
      sh_scalar[0] = 1.f/tau;
    }
    if (tid < KK) sh_tk[tid] = sh_sort[NN-1-tid];   // descending top-K
    __syncthreads();
  }
  const float invTau = sh_scalar[0];

  // ================= Gamma0 column sums Z_k =================
  {
    float z[KK];
    #pragma unroll
    for (int k=0;k<KK;k++) z[k]=0.f;
    #pragma unroll
    for (int j=0;j<RPT;j++){
      float sv = sh_s[tid+j*NT];
      #pragma unroll
      for (int k=0;k<KK;k++){
        float d = fabsf(sh_tk[k]-sv);
        float e = __expf(d*invTau);              // sigmoid(-d/tau) = 1/(1+e)
        z[k] += __fdividef(1.f, 1.f+e) + SMALL_F;
      }
    }
    #pragma unroll
    for (int k=0;k<KK;k++){
      float mv = z[k];
      #pragma unroll
      for (int o=16;o>0;o>>=1) mv += __shfl_xor_sync(0xffffffffu, mv, o);
      if (lane==0) sh_red[wid*KP1+k] = mv;
    }
    __syncthreads();
    if (tid < KK){
      float Z=0.f;
      #pragma unroll
      for (int q=0;q<NWARP;q++) Z += sh_red[q*KP1+tid];
      sh_invZn[tid] = __fdividef(1.f, Z*(float)NN);
    }
    __syncthreads();
  }

  // ================= final: Gamma, A, ||Gamma - Gamma0|| =================
  float nrm = 0.f;
  #pragma unroll 1
  for (int j=0;j<RPT;j++){
    int n = tid + j*NT;
    float sv = sh_s[n];
    float g  = y[j];
    float wj = w[j];
    float* orow = out + ((size_t)b*NN + n)*KK;
    float gam64 = g * sh_coef[0];                 // k=64 (a=0)
    float t  = wj;                                // w^a, a starting at 1
    float rs = 0.f;
    #pragma unroll
    for (int a=1;a<=KK;a++){
      int k = KK-a;
      float gam = g*t*sh_coef[a];                 // Gamma[n,k] = y * w^a * cE[a]*v[k]
      orow[k] = gam*(float)NN;                    // A = Gamma * n
      float d  = fabsf(sh_tk[k]-sv);
      float e  = __expf(d*invTau);
      float g0 = (__fdividef(1.f,1.f+e)+SMALL_F)*sh_invZn[k];
      rs += g0;
      float df = gam - g0;
      nrm = fmaf(df,df,nrm);
      t *= wj;
    }
    float last = 1.f/(float)NN - rs;
    last = fminf(fmaxf(last, SMALL_F), 1.f-SMALL_F);
    float dl = gam64 - last;
    nrm = fmaf(dl,dl,nrm);
  }
  #pragma unroll
  for (int o=16;o>0;o>>=1) nrm += __shfl_xor_sync(0xffffffffu, nrm, o);
  if (lane==0) sh_red[wid] = nrm;
  __syncthreads();
  if (tid==0){
    float s=0.f;
    for (int q=0;q<NWARP;q++) s += sh_red[q];
    g_normPart[b] = s;
  }
}

__global__ void k_norm(float* __restrict__ out){
  float s = 0.f;
  for (int b=0;b<BSZ;b++) s += g_normPart[b];   // fixed order -> deterministic
  out[(size_t)BSZ*NN*KK] = sqrtf(s);
}

extern "C" void kernel_launch(void* const* d_in, const int* in_sizes, int n_in,
                              void* d_out, int out_size)
{
  const float* scores = (const float*)d_in[0];
  const float* W      = (const float*)d_in[1];
  if (n_in >= 2 && in_sizes[0] == NN && in_sizes[1] == BSZ*NN){
    const float* tmp = scores; scores = W; W = tmp;   // defensive input-order swap
  }
  float* out = (float*)d_out;
  (void)out_size;

  k_init  <<<1, 1>>>();
  k_reduce<<<256, 256>>>(scores);
  k_params<<<1, 1>>>();
  k_main  <<<BSZ, NT>>>(scores, W, out);
  k_norm  <<<1, 1>>>(out);
}

// round 2
// speedup vs baseline: 15.9203x; 15.9203x over previous
#include <cuda_runtime.h>
#include <cstddef>

#define BSZ   256
#define NN    2048
#define KK    64
#define KP1   65
#define NT    256
#define RPT   8          // rows per thread = NN/NT
#define NWARP (NT/32)    // 8
#define RSTR  65         // padded stride for reduction rows (odd -> conflict-free)
#define MAXIT 200
#define EPS_F 0.1f
#define SMALL_F 1e-20f
#define CONV_TOL 1e-6f

typedef unsigned long long u64;

__device__ unsigned g_maxEnc;
__device__ unsigned g_minEnc;
__device__ int      g_anyMask;
__device__ float    g_alpha;
__device__ float    g_filled;
__device__ float    g_normPart[BSZ];

__device__ __forceinline__ float neg_inf_f(){ return __int_as_float(0xff800000); }

__device__ __forceinline__ u64 pack2(float lo, float hi){
  u64 r; asm("mov.b64 %0, {%1,%2};" : "=l"(r) : "f"(lo), "f"(hi)); return r;
}
__device__ __forceinline__ void unpack2(u64 v, float& lo, float& hi){
  asm("mov.b64 {%0,%1}, %2;" : "=f"(lo), "=f"(hi) : "l"(v));
}
__device__ __forceinline__ u64 fma2(u64 a, u64 b, u64 c){
  u64 d; asm("fma.rn.f32x2 %0, %1, %2, %3;" : "=l"(d) : "l"(a), "l"(b), "l"(c)); return d;
}
__device__ __forceinline__ u64 mul2(u64 a, u64 b){
  u64 d; asm("mul.rn.f32x2 %0, %1, %2;" : "=l"(d) : "l"(a), "l"(b)); return d;
}
__device__ __forceinline__ u64 add2(u64 a, u64 b){
  u64 d; asm("add.rn.f32x2 %0, %1, %2;" : "=l"(d) : "l"(a), "l"(b)); return d;
}

// order-preserving float->uint encoding (monotone increasing)
__device__ __forceinline__ unsigned encF(float f){
  unsigned u = __float_as_uint(f);
  return (u & 0x80000000u) ? ~u : (u | 0x80000000u);
}
__device__ __forceinline__ float decF(unsigned e){
  unsigned u = (e & 0x80000000u) ? (e & 0x7fffffffu) : ~e;
  return __uint_as_float(u);
}

__global__ void k_init(){
  g_maxEnc = 0u;
  g_minEnc = 0xffffffffu;
  g_anyMask = 0;
}

__global__ void k_reduce(const float* __restrict__ s){
  int i = blockIdx.x * blockDim.x + threadIdx.x;
  int stride = gridDim.x * blockDim.x;
  unsigned mx = 0u, mn = 0xffffffffu;
  unsigned any = 0u;
  float ninf = neg_inf_f();
  for (; i < BSZ*NN; i += stride){
    float x = s[i];
    bool neg = (x == ninf);
    any |= (neg ? 1u : 0u);
    unsigned e = encF(x);
    mx = max(mx, e);
    mn = min(mn, neg ? 0xffffffffu : e);
  }
  mx  = __reduce_max_sync(0xffffffffu, mx);
  mn  = __reduce_min_sync(0xffffffffu, mn);
  any = __reduce_or_sync (0xffffffffu, any);
  if ((threadIdx.x & 31) == 0){
    atomicMax(&g_maxEnc, mx);
    atomicMin(&g_minEnc, mn);
    if (any) atomicOr(&g_anyMask, 1);
  }
}

__global__ void k_params(){
  float maxS = decF(g_maxEnc);
  float minS = decF(g_minEnc);
  float filled = minS - (maxS - minS);
  float minF = g_anyMask ? fminf(filled, minS) : minS;
  float maxF = fmaxf(maxS, minF);
  float c1 = minF*minF, c2 = maxF*maxF;
  float c3 = (minF-64.f)*(minF-64.f), c4 = (maxF-64.f)*(maxF-64.f);
  float cmax = fmaxf(fmaxf(c1,c2), fmaxf(c3,c4));
  g_alpha  = 1.f/(EPS_F*cmax);
  g_filled = filled;
}

__global__ void __launch_bounds__(NT, 2) k_main(
    const float* __restrict__ scores,
    const float* __restrict__ W,
    float* __restrict__ out)
{
  __shared__ float sh_s[NN];
  __shared__ float sh_red[KP1*RSTR];   // loop: 65 rows x 64 partials (stride 65); reused as sort buffer
  __shared__ float sh_coef[KP1];       // coef[a] = cE[a]*v[64-a]
  __shared__ float sh_tk[KK];
  __shared__ float sh_invZn[KK];
  __shared__ float sh_wred[NWARP];
  __shared__ float sh_scalar[1];
  __shared__ int   sh_conv[2];

  const int b    = blockIdx.x;
  const int tid  = threadIdx.x;
  const int wid  = tid >> 5;
  const int lane = tid & 31;
  const float alpha  = g_alpha;
  const float filled = g_filled;
  const float MU = 1.f/(float)NN;
  const float ninf = neg_inf_f();

  const float* sc = scores + (size_t)b*NN;

  #pragma unroll
  for (int j=0;j<RPT;j++){
    int n = tid + j*NT;
    float x = sc[n];
    if (x == ninf) x = filled;
    sh_s[n] = x;
  }
  if (tid < KP1){
    float a  = (float)tid;
    sh_coef[tid] = __expf(-alpha*a*a) * (1.f/(float)KP1);  // cE[a] * v0, v0 = 1/65
  }
  if (tid == 0){ sh_conv[0] = 0; sh_conv[1] = 0; }
  __syncthreads();

  // w_n = exp(2*alpha*s_n), packed in pairs
  u64 w2[RPT/2];
  #pragma unroll
  for (int q=0;q<RPT/2;q++){
    float wa = __expf(2.f*alpha*sh_s[tid + (2*q  )*NT]);
    float wb = __expf(2.f*alpha*sh_s[tid + (2*q+1)*NT]);
    w2[q] = pack2(wa, wb);
  }

  float oldc = (tid < KP1) ? sh_coef[tid] : 0.f;
  u64 y2[RPT/2];

  // ================= Sinkhorn iterations (early-exit at fp32 fixed point) =============
  #pragma unroll 1
  for (int it=0; it<MAXIT; ++it){
    // ---- u-update: acc = sum_a coef[a]*w^a (Horner, packed), y = MU/acc ----
    {
      float c64 = sh_coef[KK];
      u64 acc2[RPT/2];
      #pragma unroll
      for (int q=0;q<RPT/2;q++) acc2[q] = pack2(c64, c64);
      #pragma unroll
      for (int a=KK-1;a>=0;--a){
        float f = sh_coef[a];
        u64 f2 = pack2(f, f);
        #pragma unroll
        for (int q=0;q<RPT/2;q++) acc2[q] = fma2(acc2[q], w2[q], f2);
      }
      #pragma unroll
      for (int q=0;q<RPT/2;q++){
        float lo, hi; unpack2(acc2[q], lo, hi);
        y2[q] = pack2(__fdividef(MU, lo), __fdividef(MU, hi));
      }
    }

    // ---- v-update power sums m_a = sum_n y_n w_n^a ----
    {
      u64 t2[RPT/2];
      #pragma unroll
      for (int q=0;q<RPT/2;q++) t2[q] = y2[q];
      #pragma unroll
      for (int a=0;a<KP1;a++){
        u64 p = add2(add2(t2[0], t2[1]), add2(t2[2], t2[3]));
        float lo, hi; unpack2(p, lo, hi);
        float mv = lo + hi;
        mv += __shfl_xor_sync(0xffffffffu, mv, 16);
        mv += __shfl_xor_sync(0xffffffffu, mv, 8);
        if (lane < 8) sh_red[a*RSTR + wid*8 + lane] = mv;
        if (a < KK){
          #pragma unroll
          for (int q=0;q<RPT/2;q++) t2[q] = mul2(t2[q], w2[q]);
        }
      }
    }
    __syncthreads();

    if (tid < KP1){
      float mm = 0.f;
      const float* row = &sh_red[tid*RSTR];
      #pragma unroll
      for (int p=0;p<NWARP*8;p++) mm += row[p];
      float nuv = (tid==0) ? ((float)(NN-KK)/(float)NN) : MU;
      float newc = __fdividef(nuv, mm);          // cE cancels algebraically
      sh_coef[tid] = newc;
      if (fabsf(newc - oldc) > CONV_TOL*fabsf(oldc)) sh_conv[it&1] = 1;
      oldc = newc;
      if (tid == 0) sh_conv[(it+1)&1] = 0;
    }
    __syncthreads();
    if (sh_conv[it&1] == 0) break;               // all coefs at fixed point
  }

  // ================= sort s (bitonic, ascending) in sh_red =================
  float* sh_sort = sh_red;
  #pragma unroll
  for (int j=0;j<RPT;j++) sh_sort[tid+j*NT] = sh_s[tid+j*NT];
  __syncthreads();
  for (int kk2=2; kk2<=NN; kk2<<=1){
    for (int jj=kk2>>1; jj>0; jj>>=1){
      #pragma unroll
      for (int j=0;j<RPT;j++){
        int i = tid + j*NT;
        int ixj = i ^ jj;
        if (ixj > i){
          float va = sh_sort[i], vb = sh_sort[ixj];
          bool asc = ((i & kk2) == 0);
          if ((va > vb) == asc){ sh_sort[i]=vb; sh_sort[ixj]=va; }
        }
      }
      __syncthreads();
    }
  }

  // ================= tau and top-k =================
  {
    float part = 0.f;
    #pragma unroll
    for (int j=0;j<RPT;j++){ int n=tid+j*NT; part += sh_sort[n]*W[n]; }
    #pragma unroll
    for (int o=16;o>0;o>>=1) part += __shfl_xor_sync(0xffffffffu, part, o);
    if (lane==0) sh_wred[wid] = part;
    __syncthreads();
    if (tid==0){
      float tau=0.f;
      #pragma unroll
      for (int q=0;q<NWARP;q++) tau += sh_wred[q];
      sh_scalar[0] = 1.f/tau;
    }
    if (tid < KK) sh_tk[tid] = sh_sort[NN-1-tid];   // descending top-K
    __syncthreads();
  }
  const float invTau = sh_scalar[0];

  // ================= Gamma0 column sums Z_k (chunked to keep regs low) ============
  #pragma unroll 1
  for (int c=0;c<KK/16;c++){
    float z[16];
    #pragma unroll
    for (int q=0;q<16;q++) z[q]=0.f;
    #pragma unroll
    for (int j=0;j<RPT;j++){
      float sv = sh_s[tid+j*NT];
      #pragma unroll
      for (int q=0;q<16;q++){
        float d = fabsf(sh_tk[c*16+q]-sv);
        float e = __expf(d*invTau);               // sigmoid(-d/tau) = 1/(1+e)
        z[q] += __fdividef(1.f, 1.f+e) + SMALL_F;
      }
    }
    #pragma unroll
    for (int q=0;q<16;q++){
      float mv = z[q];
      #pragma unroll
      for (int o=16;o>0;o>>=1) mv += __shfl_xor_sync(0xffffffffu, mv, o);
      if (lane==0) sh_wred[wid] = mv;   // reuse: one anchor at a time per pass would serialize; store per (q,wid)
      // instead: store to sh_red region (free after sort usage this pass? sh_sort no longer needed)
      if (lane==0) sh_red[q*NWARP + wid] = mv;
    }
    __syncthreads();
    if (tid < 16){
      float Z=0.f;
      #pragma unroll
      for (int q=0;q<NWARP;q++) Z += sh_red[tid*NWARP+q];
      sh_invZn[c*16+tid] = __fdividef(1.f, Z*(float)NN);
    }
    __syncthreads();
  }

  // ================= final: Gamma, A, ||Gamma - Gamma0|| =================
  float nrm = 0.f;
  #pragma unroll 1
  for (int j=0;j<RPT;j++){
    int n = tid + j*NT;
    float sv = sh_s[n];
    float yj, wj;
    { float lo,hi;
      unpack2(y2[j>>1], lo, hi); yj = (j&1)?hi:lo;
      unpack2(w2[j>>1], lo, hi); wj = (j&1)?hi:lo; }
    float* orow = out + ((size_t)b*NN + n)*KK;
    float gam64 = yj * sh_coef[0];               // k=64 column (a=0), norm only
    float t  = wj;                               // w^a, a starting at 1
    float rs = 0.f;
    #pragma unroll 1
    for (int g=0;g<16;g++){                      // anchors a = 4g+1 .. 4g+4 -> k = 63-4g .. 60-4g
      float gv[4];
      #pragma unroll
      for (int m=0;m<4;m++){
        int a = 4*g + 1 + m;
        int k = KK - a;
        float gam = yj*t*sh_coef[a];
        gv[m] = gam;
        float d  = fabsf(sh_tk[k]-sv);
        float e  = __expf(d*invTau);
        float g0 = (__fdividef(1.f,1.f+e)+SMALL_F)*sh_invZn[k];
        rs += g0;
        float df = gam - g0;
        nrm = fmaf(df,df,nrm);
        t *= wj;
      }
      float4 o4 = make_float4(gv[3]*(float)NN, gv[2]*(float)NN,
                              gv[1]*(float)NN, gv[0]*(float)NN);
      *reinterpret_cast<float4*>(orow + (60 - 4*g)) = o4;   // k0 = 60-4g
    }
    float last = 1.f/(float)NN - rs;
    last = fminf(fmaxf(last, SMALL_F), 1.f-SMALL_F);
    float dl = gam64 - last;
    nrm = fmaf(dl,dl,nrm);
  }
  #pragma unroll
  for (int o=16;o>0;o>>=1) nrm += __shfl_xor_sync(0xffffffffu, nrm, o);
  if (lane==0) sh_wred[wid] = nrm;
  __syncthreads();
  if (tid==0){
    float s=0.f;
    #pragma unroll
    for (int q=0;q<NWARP;q++) s += sh_wred[q];
    g_normPart[b] = s;
  }
}

__global__ void k_norm(float* __restrict__ out){
  float s = 0.f;
  for (int b=0;b<BSZ;b++) s += g_normPart[b];   // fixed order -> deterministic
  out[(size_t)BSZ*NN*KK] = sqrtf(s);
}

extern "C" void kernel_launch(void* const* d_in, const int* in_sizes, int n_in,
                              void* d_out, int out_size)
{
  const float* scores = (const float*)d_in[0];
  const float* W      = (const float*)d_in[1];
  if (n_in >= 2 && in_sizes[0] == NN && in_sizes[1] == BSZ*NN){
    const float* tmp = scores; scores = W; W = tmp;   // defensive input-order swap
  }
  float* out = (float*)d_out;
  (void)out_size;

  k_init  <<<1, 1>>>();
  k_reduce<<<256, 256>>>(scores);
  k_params<<<1, 1>>>();
  k_main  <<<BSZ, NT>>>(scores, W, out);
  k_norm  <<<1, 1>>>(out);
}